// round 2
// baseline (speedup 1.0000x reference)
#include <cuda_runtime.h>
#include <math.h>

// Problem constants
#define BSZ 8192
#define IN_DIM 2048
#define H_DIM 2048
#define CAT_DIM (IN_DIM + H_DIM)   // 4096

// Tile config
#define BM 128
#define BN 64
#define BK 16
#define TM 8
#define TN 4
#define NTHREADS 256

// Fused kernel: computes
//   acc_g[b,h] = input[b,:] . gw[h,0:2048] + state[b,:] . gw[h,2048:4096]
//   acc_v[b,h] = input[b,:] . wi[h,:]
// then the full epilogue, writing 5 of the 6 output regions.
__global__ __launch_bounds__(NTHREADS)
void fused_rnn_gemm_kernel(const float* __restrict__ input,
                           const float* __restrict__ state,
                           const float* __restrict__ gw,
                           const float* __restrict__ bias,
                           const float* __restrict__ wi,
                           float* __restrict__ out)
{
    __shared__ float As[BK][BM];
    __shared__ float Bg[BK][BN];
    __shared__ float Bv[BK][BN];

    const int tid = threadIdx.x;
    const int tx = tid & 15;          // 0..15 -> column group (TN=4)
    const int ty = tid >> 4;          // 0..15 -> row group (TM=8)

    const int blockM = blockIdx.y * BM;
    const int blockN = blockIdx.x * BN;
    const int rowBase = blockM + ty * TM;
    const int colBase = blockN + tx * TN;

    // loader indexing: 256 threads, float4 granularity
    const int lr = tid >> 2;          // 0..63
    const int lc = (tid & 3) * 4;     // 0,4,8,12

    float acc_g[TM][TN];
    float acc_v[TM][TN];
#pragma unroll
    for (int i = 0; i < TM; i++)
#pragma unroll
        for (int j = 0; j < TN; j++) { acc_g[i][j] = 0.f; acc_v[i][j] = 0.f; }

    const float* A0 = input + (size_t)blockM * IN_DIM;
    const float* S0 = state + (size_t)blockM * H_DIM;
    const float* G0 = gw + (size_t)blockN * CAT_DIM;
    const float* V0 = wi + (size_t)blockN * IN_DIM;

    // ---------------- Phase 1: k over input (both accumulators) ----------------
    for (int k0 = 0; k0 < IN_DIM; k0 += BK) {
        // A tile (128 x 16), transposed into smem
#pragma unroll
        for (int r = 0; r < 2; r++) {
            int row = lr + r * 64;
            float4 a4 = *(const float4*)(A0 + (size_t)row * IN_DIM + k0 + lc);
            As[lc + 0][row] = a4.x; As[lc + 1][row] = a4.y;
            As[lc + 2][row] = a4.z; As[lc + 3][row] = a4.w;
        }
        // B tiles (64 x 16)
        {
            float4 g4 = *(const float4*)(G0 + (size_t)lr * CAT_DIM + k0 + lc);
            Bg[lc + 0][lr] = g4.x; Bg[lc + 1][lr] = g4.y;
            Bg[lc + 2][lr] = g4.z; Bg[lc + 3][lr] = g4.w;
            float4 v4 = *(const float4*)(V0 + (size_t)lr * IN_DIM + k0 + lc);
            Bv[lc + 0][lr] = v4.x; Bv[lc + 1][lr] = v4.y;
            Bv[lc + 2][lr] = v4.z; Bv[lc + 3][lr] = v4.w;
        }
        __syncthreads();

#pragma unroll
        for (int k = 0; k < BK; k++) {
            float a[TM], bg[TN], bv[TN];
#pragma unroll
            for (int i = 0; i < TM; i++) a[i] = As[k][ty * TM + i];
#pragma unroll
            for (int j = 0; j < TN; j++) { bg[j] = Bg[k][tx * TN + j]; bv[j] = Bv[k][tx * TN + j]; }
#pragma unroll
            for (int i = 0; i < TM; i++)
#pragma unroll
                for (int j = 0; j < TN; j++) {
                    acc_g[i][j] = fmaf(a[i], bg[j], acc_g[i][j]);
                    acc_v[i][j] = fmaf(a[i], bv[j], acc_v[i][j]);
                }
        }
        __syncthreads();
    }

    // ---------------- Phase 2: k over state (gate accumulator only) ----------------
    for (int k0 = 0; k0 < H_DIM; k0 += BK) {
#pragma unroll
        for (int r = 0; r < 2; r++) {
            int row = lr + r * 64;
            float4 a4 = *(const float4*)(S0 + (size_t)row * H_DIM + k0 + lc);
            As[lc + 0][row] = a4.x; As[lc + 1][row] = a4.y;
            As[lc + 2][row] = a4.z; As[lc + 3][row] = a4.w;
        }
        {
            float4 g4 = *(const float4*)(G0 + (size_t)lr * CAT_DIM + IN_DIM + k0 + lc);
            Bg[lc + 0][lr] = g4.x; Bg[lc + 1][lr] = g4.y;
            Bg[lc + 2][lr] = g4.z; Bg[lc + 3][lr] = g4.w;
        }
        __syncthreads();

#pragma unroll
        for (int k = 0; k < BK; k++) {
            float a[TM], bg[TN];
#pragma unroll
            for (int i = 0; i < TM; i++) a[i] = As[k][ty * TM + i];
#pragma unroll
            for (int j = 0; j < TN; j++) bg[j] = Bg[k][tx * TN + j];
#pragma unroll
            for (int i = 0; i < TM; i++)
#pragma unroll
                for (int j = 0; j < TN; j++)
                    acc_g[i][j] = fmaf(a[i], bg[j], acc_g[i][j]);
        }
        __syncthreads();
    }

    // ---------------- Epilogue ----------------
    // Output layout (floats): new_h | concat | pre_gate | gate | values | pre_h
    const size_t BH = (size_t)BSZ * H_DIM;
    const size_t BC = (size_t)BSZ * CAT_DIM;
    float* out_newh = out;
    float* out_pg   = out + BH + BC;
    float* out_gate = out_pg + BH;
    float* out_val  = out_gate + BH;
    float* out_ph   = out_val + BH;

    float4 b4 = *(const float4*)(bias + colBase);
    const float bb[4] = { b4.x, b4.y, b4.z, b4.w };

#pragma unroll
    for (int i = 0; i < TM; i++) {
        const int row = rowBase + i;
        const size_t off = (size_t)row * H_DIM + colBase;
        float4 s4 = *(const float4*)(state + off);
        const float ss[4] = { s4.x, s4.y, s4.z, s4.w };

        float4 pg4, g4o, v4o, ph4, nh4;
        float* pgp = (float*)&pg4; float* gp = (float*)&g4o;
        float* vp = (float*)&v4o;  float* php = (float*)&ph4; float* nhp = (float*)&nh4;
#pragma unroll
        for (int j = 0; j < TN; j++) {
            float pg = acc_g[i][j] + bb[j];
            float g  = fminf(fmaxf(pg, 0.f), 1.f);
            float v  = tanhf(acc_v[i][j]);
            float ph = ss[j] * (1.f - g) + v * g;
            float nh = fmaxf(ph, 0.f);
            pgp[j] = pg; gp[j] = g; vp[j] = v; php[j] = ph; nhp[j] = nh;
        }
        *(float4*)(out_newh + off) = nh4;
        *(float4*)(out_pg   + off) = pg4;
        *(float4*)(out_gate + off) = g4o;
        *(float4*)(out_val  + off) = v4o;
        *(float4*)(out_ph   + off) = ph4;
    }
}

// concat_input = [input | state], written as region 2 of the output buffer
__global__ void concat_copy_kernel(const float* __restrict__ input,
                                   const float* __restrict__ state,
                                   float* __restrict__ concat_out)
{
    const int COLS4 = CAT_DIM / 4;      // 1024 float4 per row
    const int HALF4 = IN_DIM / 4;       // 512
    size_t idx = (size_t)blockIdx.x * blockDim.x + threadIdx.x;
    const size_t total = (size_t)BSZ * COLS4;
    if (idx >= total) return;
    size_t b = idx / COLS4;
    int c = (int)(idx % COLS4);
    float4 v;
    if (c < HALF4)
        v = *(const float4*)(input + b * IN_DIM + (size_t)c * 4);
    else
        v = *(const float4*)(state + b * H_DIM + (size_t)(c - HALF4) * 4);
    *(float4*)(concat_out + b * CAT_DIM + (size_t)c * 4) = v;
}

extern "C" void kernel_launch(void* const* d_in, const int* in_sizes, int n_in,
                              void* d_out, int out_size)
{
    const float* input = (const float*)d_in[0];
    const float* state = (const float*)d_in[1];
    const float* gw    = (const float*)d_in[2];
    const float* bias  = (const float*)d_in[3];
    const float* wi    = (const float*)d_in[4];
    float* out = (float*)d_out;

    // Fused GEMM + epilogue
    dim3 grid(H_DIM / BN, BSZ / BM);   // (32, 64)
    fused_rnn_gemm_kernel<<<grid, NTHREADS>>>(input, state, gw, bias, wi, out);

    // concat region starts after new_h
    float* concat_out = out + (size_t)BSZ * H_DIM;
    const size_t total4 = (size_t)BSZ * (CAT_DIM / 4);
    int threads = 256;
    int blocks = (int)((total4 + threads - 1) / threads);
    concat_copy_kernel<<<blocks, threads>>>(input, state, concat_out);
}

// round 4
// speedup vs baseline: 1.7544x; 1.7544x over previous
#include <cuda_runtime.h>
#include <cstdint>
#include <math.h>

// ---------------- problem constants ----------------
#define BSZ   8192
#define IN_D  2048
#define H_D   2048
#define CAT_D 4096

// ---------------- GEMM tile config ----------------
#define BM 128
#define BN 128
#define BK 32
#define LDSW 36            // BK + 4 pad, in floats (conflict-free, 8B-aligned rows)
#define NT 256

// ---------------- helpers ----------------
__device__ __forceinline__ uint32_t smem_u32(const void* p) {
    uint32_t a;
    asm("{ .reg .u64 t; cvta.to.shared.u64 t, %1; cvt.u32.u64 %0, t; }" : "=r"(a) : "l"(p));
    return a;
}
__device__ __forceinline__ void cp8(uint32_t dst, const void* src) {
    asm volatile("cp.async.ca.shared.global [%0], [%1], 8;" :: "r"(dst), "l"(src) : "memory");
}
#define CP_COMMIT() asm volatile("cp.async.commit_group;" ::: "memory")
#define CP_WAIT1()  asm volatile("cp.async.wait_group 1;" ::: "memory")
#define CP_WAIT0()  asm volatile("cp.async.wait_group 0;" ::: "memory")

__device__ __forceinline__ uint32_t f2tf(float f) {
    uint32_t r; asm("cvt.rna.tf32.f32 %0, %1;" : "=r"(r) : "f"(f)); return r;
}
__device__ __forceinline__ void mma8(float* d, const uint32_t* a, const uint32_t* b) {
    asm volatile(
        "mma.sync.aligned.m16n8k8.row.col.f32.tf32.tf32.f32 "
        "{%0,%1,%2,%3}, {%4,%5,%6,%7}, {%8,%9}, {%0,%1,%2,%3};"
        : "+f"(d[0]), "+f"(d[1]), "+f"(d[2]), "+f"(d[3])
        : "r"(a[0]), "r"(a[1]), "r"(a[2]), "r"(a[3]), "r"(b[0]), "r"(b[1]));
}

// ---------------- stage loader ----------------
template<bool GATE>
__device__ __forceinline__ void load_stage(float* smA, float* smB,
        const float* __restrict__ input, const float* __restrict__ state,
        const float* __restrict__ W,
        int blockM, int blockN, int k0, int tid)
{
    const int row = tid >> 1;          // 0..127
    const int u0 = (tid & 1) * 8;      // 8B-unit offset

    const float* Aptr = input;
    int ka = k0;
    if (GATE && k0 >= IN_D) { Aptr = state; ka = k0 - IN_D; }
    const float* asrc = Aptr + (size_t)(blockM + row) * 2048 + ka;
    const size_t bld = GATE ? (size_t)CAT_D : (size_t)IN_D;
    const float* bsrc = W + (size_t)(blockN + row) * bld + k0;

    uint32_t adst = smem_u32(smA + (size_t)row * LDSW);
    uint32_t bdst = smem_u32(smB + (size_t)row * LDSW);
#pragma unroll
    for (int j = 0; j < 8; j++) {
        const int u = u0 + j;          // 8B unit 0..15 within the 128B row
        cp8(adst + (uint32_t)u * 8, asrc + u * 2);
        cp8(bdst + (uint32_t)u * 8, bsrc + u * 2);
    }
}

// ---------------- stage compute ----------------
__device__ __forceinline__ void compute_stage(const float* smA, const float* smB,
        float acc[4][4][4], int m0, int n0, int g, int tig)
{
#pragma unroll
    for (int kk = 0; kk < 4; kk++) {
        uint32_t af[4][4], bf[4][2];
#pragma unroll
        for (int i = 0; i < 4; i++) {
            const float* base = smA + (size_t)(m0 + i * 16 + g) * LDSW + kk * 8 + tig;
            af[i][0] = f2tf(base[0]);
            af[i][1] = f2tf(base[8 * LDSW]);
            af[i][2] = f2tf(base[4]);
            af[i][3] = f2tf(base[8 * LDSW + 4]);
        }
#pragma unroll
        for (int j = 0; j < 4; j++) {
            const float* base = smB + (size_t)(n0 + j * 8 + g) * LDSW + kk * 8 + tig;
            bf[j][0] = f2tf(base[0]);
            bf[j][1] = f2tf(base[4]);
        }
#pragma unroll
        for (int i = 0; i < 4; i++)
#pragma unroll
            for (int j = 0; j < 4; j++)
                mma8(acc[i][j], af[i], bf[j]);
    }
}

// ---------------- GEMM kernels ----------------
// Output layout (floats): new_h | concat | pre_gate | gate | values | pre_h
template<bool GATE>
__global__ __launch_bounds__(NT, 1)
void gemm_kernel(const float* __restrict__ input, const float* __restrict__ state,
                 const float* __restrict__ W, const float* __restrict__ bias,
                 float* __restrict__ out)
{
    extern __shared__ float sm[];
    const int tid = threadIdx.x;
    const int wid = tid >> 5, lane = tid & 31;
    const int g = lane >> 2, tig = lane & 3;
    const int m0 = (wid >> 2) * 64;    // warp tile M origin (0 or 64)
    const int n0 = (wid & 3) * 32;     // warp tile N origin
    const int blockM = blockIdx.y * BM;
    const int blockN = blockIdx.x * BN;

    const int KT = (GATE ? CAT_D : IN_D) / BK;

    float* A0 = sm;
    float* B0 = sm + BM * LDSW;
    float* A1 = sm + (BM + BN) * LDSW;
    float* B1 = A1 + BM * LDSW;

    float acc[4][4][4];
#pragma unroll
    for (int i = 0; i < 4; i++)
#pragma unroll
        for (int j = 0; j < 4; j++)
#pragma unroll
            for (int t = 0; t < 4; t++) acc[i][j][t] = 0.f;

    load_stage<GATE>(A0, B0, input, state, W, blockM, blockN, 0, tid);
    CP_COMMIT();

    for (int kt = 0; kt < KT; kt++) {
        float* cA = (kt & 1) ? A1 : A0;
        float* cB = (kt & 1) ? B1 : B0;
        if (kt + 1 < KT) {
            float* nA = (kt & 1) ? A0 : A1;
            float* nB = (kt & 1) ? B0 : B1;
            load_stage<GATE>(nA, nB, input, state, W, blockM, blockN, (kt + 1) * BK, tid);
            CP_COMMIT();
            CP_WAIT1();
        } else {
            CP_WAIT0();
        }
        __syncthreads();
        compute_stage(cA, cB, acc, m0, n0, g, tig);
        __syncthreads();
    }

    // ---------------- fused epilogue ----------------
    const size_t BH = (size_t)BSZ * H_D;
    const size_t BC = (size_t)BSZ * CAT_D;

    if (GATE) {
        float* out_pg = out + BH + BC;
        float* out_gt = out_pg + BH;
#pragma unroll
        for (int i = 0; i < 4; i++) {
            const int r0 = blockM + m0 + i * 16 + g;
#pragma unroll
            for (int j = 0; j < 4; j++) {
                const int c = blockN + n0 + j * 8 + tig * 2;
                const float b0 = bias[c], b1 = bias[c + 1];
                float pg0 = acc[i][j][0] + b0, pg1 = acc[i][j][1] + b1;
                float pg2 = acc[i][j][2] + b0, pg3 = acc[i][j][3] + b1;
                const size_t o0 = (size_t)r0 * H_D + c;
                const size_t o1 = (size_t)(r0 + 8) * H_D + c;
                *(float2*)(out_pg + o0) = make_float2(pg0, pg1);
                *(float2*)(out_pg + o1) = make_float2(pg2, pg3);
                *(float2*)(out_gt + o0) = make_float2(fminf(fmaxf(pg0, 0.f), 1.f),
                                                      fminf(fmaxf(pg1, 0.f), 1.f));
                *(float2*)(out_gt + o1) = make_float2(fminf(fmaxf(pg2, 0.f), 1.f),
                                                      fminf(fmaxf(pg3, 0.f), 1.f));
            }
        }
    } else {
        float* out_val = out + 3 * BH + BC;
#pragma unroll
        for (int i = 0; i < 4; i++) {
            const int r0 = blockM + m0 + i * 16 + g;
#pragma unroll
            for (int j = 0; j < 4; j++) {
                const int c = blockN + n0 + j * 8 + tig * 2;
                const size_t o0 = (size_t)r0 * H_D + c;
                const size_t o1 = (size_t)(r0 + 8) * H_D + c;
                *(float2*)(out_val + o0) = make_float2(tanhf(acc[i][j][0]), tanhf(acc[i][j][1]));
                *(float2*)(out_val + o1) = make_float2(tanhf(acc[i][j][2]), tanhf(acc[i][j][3]));
            }
        }
    }
}

// ---------------- final elementwise: pre_h, new_h ----------------
__global__ void final_kernel(const float* __restrict__ state, float* __restrict__ out)
{
    const size_t BH = (size_t)BSZ * H_D;
    const size_t BC = (size_t)BSZ * CAT_D;
    const size_t n4 = BH / 4;
    size_t i = (size_t)blockIdx.x * blockDim.x + threadIdx.x;
    if (i >= n4) return;
    const float4 s = ((const float4*)state)[i];
    const float4 gv = ((const float4*)(out + 2 * BH + BC))[i];
    const float4 vv = ((const float4*)(out + 3 * BH + BC))[i];
    float4 ph, nh;
    ph.x = s.x * (1.f - gv.x) + vv.x * gv.x; nh.x = fmaxf(ph.x, 0.f);
    ph.y = s.y * (1.f - gv.y) + vv.y * gv.y; nh.y = fmaxf(ph.y, 0.f);
    ph.z = s.z * (1.f - gv.z) + vv.z * gv.z; nh.z = fmaxf(ph.z, 0.f);
    ph.w = s.w * (1.f - gv.w) + vv.w * gv.w; nh.w = fmaxf(ph.w, 0.f);
    ((float4*)(out + 4 * BH + BC))[i] = ph;
    ((float4*)out)[i] = nh;
}

// ---------------- concat kernel ----------------
__global__ void concat_copy_kernel(const float* __restrict__ input,
                                   const float* __restrict__ state,
                                   float* __restrict__ concat_out)
{
    const int COLS4 = CAT_D / 4;
    const int HALF4 = IN_D / 4;
    size_t idx = (size_t)blockIdx.x * blockDim.x + threadIdx.x;
    const size_t total = (size_t)BSZ * COLS4;
    if (idx >= total) return;
    size_t b = idx / COLS4;
    int c = (int)(idx % COLS4);
    float4 v;
    if (c < HALF4) v = *(const float4*)(input + b * IN_D + (size_t)c * 4);
    else           v = *(const float4*)(state + b * H_D + (size_t)(c - HALF4) * 4);
    *(float4*)(concat_out + b * CAT_D + (size_t)c * 4) = v;
}

extern "C" void kernel_launch(void* const* d_in, const int* in_sizes, int n_in,
                              void* d_out, int out_size)
{
    const float* input = (const float*)d_in[0];
    const float* state = (const float*)d_in[1];
    const float* gw    = (const float*)d_in[2];
    const float* bias  = (const float*)d_in[3];
    const float* wi    = (const float*)d_in[4];
    float* out = (float*)d_out;

    const int smem_bytes = 2 * (BM + BN) * LDSW * sizeof(float);   // 73728
    cudaFuncSetAttribute(gemm_kernel<true>,  cudaFuncAttributeMaxDynamicSharedMemorySize, smem_bytes);
    cudaFuncSetAttribute(gemm_kernel<false>, cudaFuncAttributeMaxDynamicSharedMemorySize, smem_bytes);

    dim3 grid(H_D / BN, BSZ / BM);   // (16, 64)
    gemm_kernel<true><<<grid, NT, smem_bytes>>>(input, state, gw, bias, out);
    gemm_kernel<false><<<grid, NT, smem_bytes>>>(input, state, wi, bias, out);

    const size_t BH = (size_t)BSZ * H_D;
    final_kernel<<<(int)((BH / 4 + 255) / 256), 256>>>(state, out);

    float* concat_out = out + BH;
    const size_t total4 = (size_t)BSZ * (CAT_D / 4);
    concat_copy_kernel<<<(int)((total4 + 255) / 256), 256>>>(input, state, concat_out);
}

// round 5
// speedup vs baseline: 2.3313x; 1.3289x over previous
#include <cuda_runtime.h>
#include <cstdint>
#include <math.h>

// ---------------- problem constants ----------------
#define BSZ   8192
#define IN_D  2048
#define H_D   2048
#define CAT_D 4096

// ---------------- GEMM tile config ----------------
#define BM 128
#define BN 256
#define BK 32
#define LDSW 36            // BK + 4 pad (floats); 144B row stride, 16B aligned
#define NT 256

// ---------------- tf32-rounded scratch ----------------
__device__ float g_cvt_in[(size_t)BSZ * IN_D];
__device__ float g_cvt_st[(size_t)BSZ * H_D];
__device__ float g_cvt_gw[(size_t)H_D * CAT_D];
__device__ float g_cvt_wi[(size_t)H_D * IN_D];

// ---------------- helpers ----------------
__device__ __forceinline__ uint32_t smem_u32(const void* p) {
    uint32_t a;
    asm("{ .reg .u64 t; cvta.to.shared.u64 t, %1; cvt.u32.u64 %0, t; }" : "=r"(a) : "l"(p));
    return a;
}
__device__ __forceinline__ void cp16(uint32_t dst, const void* src) {
    asm volatile("cp.async.cg.shared.global [%0], [%1], 16;" :: "r"(dst), "l"(src) : "memory");
}
#define CP_COMMIT() asm volatile("cp.async.commit_group;" ::: "memory")
#define CP_WAIT1()  asm volatile("cp.async.wait_group 1;" ::: "memory")
#define CP_WAIT0()  asm volatile("cp.async.wait_group 0;" ::: "memory")

__device__ __forceinline__ void mma8(float* d, const uint32_t* a, const uint32_t* b) {
    asm volatile(
        "mma.sync.aligned.m16n8k8.row.col.f32.tf32.tf32.f32 "
        "{%0,%1,%2,%3}, {%4,%5,%6,%7}, {%8,%9}, {%0,%1,%2,%3};"
        : "+f"(d[0]), "+f"(d[1]), "+f"(d[2]), "+f"(d[3])
        : "r"(a[0]), "r"(a[1]), "r"(a[2]), "r"(a[3]), "r"(b[0]), "r"(b[1]));
}

// ---------------- tf32 pre-round ----------------
__global__ void tf32_round_kernel(const float4* __restrict__ src, float4* __restrict__ dst, int n4) {
    int i = blockIdx.x * blockDim.x + threadIdx.x;
    if (i >= n4) return;
    float4 v = src[i];
    uint32_t a, b, c, d;
    asm("cvt.rna.tf32.f32 %0, %1;" : "=r"(a) : "f"(v.x));
    asm("cvt.rna.tf32.f32 %0, %1;" : "=r"(b) : "f"(v.y));
    asm("cvt.rna.tf32.f32 %0, %1;" : "=r"(c) : "f"(v.z));
    asm("cvt.rna.tf32.f32 %0, %1;" : "=r"(d) : "f"(v.w));
    float4 o;
    o.x = __uint_as_float(a); o.y = __uint_as_float(b);
    o.z = __uint_as_float(c); o.w = __uint_as_float(d);
    dst[i] = o;
}

// ---------------- stage loader (pre-rounded sources) ----------------
template<bool GATE>
__device__ __forceinline__ void load_stage(float* smA, float* smB,
        const float* __restrict__ W, int blockM, int blockN, int k0, int tid)
{
    const int row = tid >> 1;          // 0..127
    const int u0 = (tid & 1) * 4;      // 16B-unit offset (units of 16B)

    const float* Aptr = g_cvt_in;
    int ka = k0;
    if (GATE && k0 >= IN_D) { Aptr = g_cvt_st; ka = k0 - IN_D; }
    const float* asrc = Aptr + (size_t)(blockM + row) * 2048 + ka;
    const size_t bld = GATE ? (size_t)CAT_D : (size_t)IN_D;
    const float* bsrc0 = W + (size_t)(blockN + row) * bld + k0;
    const float* bsrc1 = W + (size_t)(blockN + row + 128) * bld + k0;

    uint32_t adst  = smem_u32(smA + (size_t)row * LDSW);
    uint32_t bdst0 = smem_u32(smB + (size_t)row * LDSW);
    uint32_t bdst1 = smem_u32(smB + (size_t)(row + 128) * LDSW);
#pragma unroll
    for (int j = 0; j < 4; j++) {
        const int u = u0 ^ j;  // wait, ensure distinct: u0 in {0,4}, j 0..3 -> u0+j
        (void)u;
    }
#pragma unroll
    for (int j = 0; j < 4; j++) {
        const int u = u0 + j;          // 16B unit 0..7 within the 128B row
        cp16(adst  + (uint32_t)u * 16, asrc  + u * 4);
        cp16(bdst0 + (uint32_t)u * 16, bsrc0 + u * 4);
        cp16(bdst1 + (uint32_t)u * 16, bsrc1 + u * 4);
    }
}

// ---------------- stage compute: warp tile 64x64 ----------------
__device__ __forceinline__ void compute_stage(const float* smA, const float* smB,
        float acc[4][8][4], int m0, int n0, int g, int tig)
{
#pragma unroll
    for (int kk = 0; kk < 4; kk++) {
        uint32_t af[4][4], bf[8][2];
#pragma unroll
        for (int i = 0; i < 4; i++) {
            const float* base = smA + (size_t)(m0 + i * 16 + g) * LDSW + kk * 8 + tig;
            af[i][0] = __float_as_uint(base[0]);
            af[i][1] = __float_as_uint(base[8 * LDSW]);
            af[i][2] = __float_as_uint(base[4]);
            af[i][3] = __float_as_uint(base[8 * LDSW + 4]);
        }
#pragma unroll
        for (int j = 0; j < 8; j++) {
            const float* base = smB + (size_t)(n0 + j * 8 + g) * LDSW + kk * 8 + tig;
            bf[j][0] = __float_as_uint(base[0]);
            bf[j][1] = __float_as_uint(base[4]);
        }
#pragma unroll
        for (int i = 0; i < 4; i++)
#pragma unroll
            for (int j = 0; j < 8; j++)
                mma8(acc[i][j], af[i], bf[j]);
    }
}

// Output layout (floats): new_h | concat | pre_gate | gate | values | pre_h
template<bool GATE>
__global__ __launch_bounds__(NT, 1)
void gemm_kernel(const float* __restrict__ state,
                 const float* __restrict__ W, const float* __restrict__ bias,
                 float* __restrict__ out)
{
    extern __shared__ float sm[];
    const int tid = threadIdx.x;
    const int wid = tid >> 5, lane = tid & 31;
    const int g = lane >> 2, tig = lane & 3;
    const int m0 = (wid >> 2) * 64;    // 0 or 64
    const int n0 = (wid & 3) * 64;     // 0..192
    const int blockM = blockIdx.y * BM;
    const int blockN = blockIdx.x * BN;

    const int KT = (GATE ? CAT_D : IN_D) / BK;

    float* A0 = sm;
    float* B0 = sm + BM * LDSW;
    float* A1 = sm + (BM + BN) * LDSW;
    float* B1 = A1 + BM * LDSW;

    float acc[4][8][4];
#pragma unroll
    for (int i = 0; i < 4; i++)
#pragma unroll
        for (int j = 0; j < 8; j++)
#pragma unroll
            for (int t = 0; t < 4; t++) acc[i][j][t] = 0.f;

    load_stage<GATE>(A0, B0, W, blockM, blockN, 0, tid);
    CP_COMMIT();

    for (int kt = 0; kt < KT; kt++) {
        float* cA = (kt & 1) ? A1 : A0;
        float* cB = (kt & 1) ? B1 : B0;
        if (kt + 1 < KT) {
            float* nA = (kt & 1) ? A0 : A1;
            float* nB = (kt & 1) ? B0 : B1;
            load_stage<GATE>(nA, nB, W, blockM, blockN, (kt + 1) * BK, tid);
            CP_COMMIT();
            CP_WAIT1();
        } else {
            CP_WAIT0();
        }
        __syncthreads();
        compute_stage(cA, cB, acc, m0, n0, g, tig);
        __syncthreads();
    }

    // ---------------- fused epilogue ----------------
    const size_t BH = (size_t)BSZ * H_D;
    const size_t BC = (size_t)BSZ * CAT_D;

    if (GATE) {
        float* out_pg = out + BH + BC;
        float* out_gt = out_pg + BH;
#pragma unroll
        for (int i = 0; i < 4; i++) {
            const int r0 = blockM + m0 + i * 16 + g;
#pragma unroll
            for (int j = 0; j < 8; j++) {
                const int c = blockN + n0 + j * 8 + tig * 2;
                const float b0 = bias[c], b1 = bias[c + 1];
                float pg0 = acc[i][j][0] + b0, pg1 = acc[i][j][1] + b1;
                float pg2 = acc[i][j][2] + b0, pg3 = acc[i][j][3] + b1;
                const size_t o0 = (size_t)r0 * H_D + c;
                const size_t o1 = (size_t)(r0 + 8) * H_D + c;
                *(float2*)(out_pg + o0) = make_float2(pg0, pg1);
                *(float2*)(out_pg + o1) = make_float2(pg2, pg3);
                *(float2*)(out_gt + o0) = make_float2(fminf(fmaxf(pg0, 0.f), 1.f),
                                                      fminf(fmaxf(pg1, 0.f), 1.f));
                *(float2*)(out_gt + o1) = make_float2(fminf(fmaxf(pg2, 0.f), 1.f),
                                                      fminf(fmaxf(pg3, 0.f), 1.f));
            }
        }
    } else {
        // value kernel runs AFTER gate kernel: gate region of out is final.
        float* out_newh = out;
        float* out_gt   = out + 2 * BH + BC;
        float* out_val  = out + 3 * BH + BC;
        float* out_ph   = out + 4 * BH + BC;
#pragma unroll
        for (int i = 0; i < 4; i++) {
            const int r0 = blockM + m0 + i * 16 + g;
#pragma unroll
            for (int j = 0; j < 8; j++) {
                const int c = blockN + n0 + j * 8 + tig * 2;
                const size_t o0 = (size_t)r0 * H_D + c;
                const size_t o1 = (size_t)(r0 + 8) * H_D + c;
                float v0 = tanhf(acc[i][j][0]), v1 = tanhf(acc[i][j][1]);
                float v2 = tanhf(acc[i][j][2]), v3 = tanhf(acc[i][j][3]);
                float2 ga = *(const float2*)(out_gt + o0);
                float2 gb = *(const float2*)(out_gt + o1);
                float2 sa = *(const float2*)(state + o0);
                float2 sb = *(const float2*)(state + o1);
                float ph0 = sa.x * (1.f - ga.x) + v0 * ga.x;
                float ph1 = sa.y * (1.f - ga.y) + v1 * ga.y;
                float ph2 = sb.x * (1.f - gb.x) + v2 * gb.x;
                float ph3 = sb.y * (1.f - gb.y) + v3 * gb.y;
                *(float2*)(out_val + o0) = make_float2(v0, v1);
                *(float2*)(out_val + o1) = make_float2(v2, v3);
                *(float2*)(out_ph + o0) = make_float2(ph0, ph1);
                *(float2*)(out_ph + o1) = make_float2(ph2, ph3);
                *(float2*)(out_newh + o0) = make_float2(fmaxf(ph0, 0.f), fmaxf(ph1, 0.f));
                *(float2*)(out_newh + o1) = make_float2(fmaxf(ph2, 0.f), fmaxf(ph3, 0.f));
            }
        }
    }
}

// ---------------- concat kernel ----------------
__global__ void concat_copy_kernel(const float* __restrict__ input,
                                   const float* __restrict__ state,
                                   float* __restrict__ concat_out)
{
    const int COLS4 = CAT_D / 4;
    const int HALF4 = IN_D / 4;
    size_t idx = (size_t)blockIdx.x * blockDim.x + threadIdx.x;
    const size_t total = (size_t)BSZ * COLS4;
    if (idx >= total) return;
    size_t b = idx / COLS4;
    int c = (int)(idx % COLS4);
    float4 v;
    if (c < HALF4) v = *(const float4*)(input + b * IN_D + (size_t)c * 4);
    else           v = *(const float4*)(state + b * H_D + (size_t)(c - HALF4) * 4);
    *(float4*)(concat_out + b * CAT_D + (size_t)c * 4) = v;
}

extern "C" void kernel_launch(void* const* d_in, const int* in_sizes, int n_in,
                              void* d_out, int out_size)
{
    const float* input = (const float*)d_in[0];
    const float* state = (const float*)d_in[1];
    const float* gw    = (const float*)d_in[2];
    const float* bias  = (const float*)d_in[3];
    const float* wi    = (const float*)d_in[4];
    float* out = (float*)d_out;

    void *p_in, *p_st, *p_gw, *p_wi;
    cudaGetSymbolAddress(&p_in, g_cvt_in);
    cudaGetSymbolAddress(&p_st, g_cvt_st);
    cudaGetSymbolAddress(&p_gw, g_cvt_gw);
    cudaGetSymbolAddress(&p_wi, g_cvt_wi);

    {
        int n4 = BSZ * IN_D / 4;
        tf32_round_kernel<<<(n4 + 255) / 256, 256>>>((const float4*)input, (float4*)p_in, n4);
        n4 = BSZ * H_D / 4;
        tf32_round_kernel<<<(n4 + 255) / 256, 256>>>((const float4*)state, (float4*)p_st, n4);
        n4 = H_D * CAT_D / 4;
        tf32_round_kernel<<<(n4 + 255) / 256, 256>>>((const float4*)gw, (float4*)p_gw, n4);
        n4 = H_D * IN_D / 4;
        tf32_round_kernel<<<(n4 + 255) / 256, 256>>>((const float4*)wi, (float4*)p_wi, n4);
    }

    const int smem_bytes = 2 * (BM + BN) * LDSW * sizeof(float);   // 110592
    cudaFuncSetAttribute(gemm_kernel<true>,  cudaFuncAttributeMaxDynamicSharedMemorySize, smem_bytes);
    cudaFuncSetAttribute(gemm_kernel<false>, cudaFuncAttributeMaxDynamicSharedMemorySize, smem_bytes);

    dim3 grid(H_D / BN, BSZ / BM);   // (8, 64)
    gemm_kernel<true><<<grid, NT, smem_bytes>>>(state, gw, bias, out);
    gemm_kernel<false><<<grid, NT, smem_bytes>>>(state, wi, bias, out);

    const size_t BH = (size_t)BSZ * H_D;
    float* concat_out = out + BH;
    const size_t total4 = (size_t)BSZ * (CAT_D / 4);
    concat_copy_kernel<<<(int)((total4 + 255) / 256), 256>>>(input, state, concat_out);
}

// round 9
// speedup vs baseline: 2.4783x; 1.0631x over previous
#include <cuda_runtime.h>
#include <cstdint>
#include <math.h>

// ---------------- problem constants ----------------
#define BSZ   8192
#define IN_D  2048
#define H_D   2048
#define CAT_D 4096

// ---------------- GEMM tile config ----------------
#define BM 128
#define BN 128
#define BK 32
#define LDSW 36            // BK + 4 pad (floats)
#define NT 256

// ---------------- tf32-rounded scratch ----------------
__device__ float g_cvt_in[(size_t)BSZ * IN_D];
__device__ float g_cvt_st[(size_t)BSZ * H_D];
__device__ float g_cvt_gw[(size_t)H_D * CAT_D];
__device__ float g_cvt_wi[(size_t)H_D * IN_D];

// ---------------- helpers ----------------
__device__ __forceinline__ uint32_t smem_u32(const void* p) {
    uint32_t a;
    asm("{ .reg .u64 t; cvta.to.shared.u64 t, %1; cvt.u32.u64 %0, t; }" : "=r"(a) : "l"(p));
    return a;
}
__device__ __forceinline__ void cp16(uint32_t dst, const void* src) {
    asm volatile("cp.async.cg.shared.global [%0], [%1], 16;" :: "r"(dst), "l"(src) : "memory");
}
#define CP_COMMIT() asm volatile("cp.async.commit_group;" ::: "memory")
#define CP_WAIT0()  asm volatile("cp.async.wait_group 0;" ::: "memory")

__device__ __forceinline__ void mma8(float* d, const uint32_t* a, const uint32_t* b) {
    asm volatile(
        "mma.sync.aligned.m16n8k8.row.col.f32.tf32.tf32.f32 "
        "{%0,%1,%2,%3}, {%4,%5,%6,%7}, {%8,%9}, {%0,%1,%2,%3};"
        : "+f"(d[0]), "+f"(d[1]), "+f"(d[2]), "+f"(d[3])
        : "r"(a[0]), "r"(a[1]), "r"(a[2]), "r"(a[3]), "r"(b[0]), "r"(b[1]));
}

// ---------------- tf32 pre-round ----------------
__global__ void tf32_round_kernel(const float4* __restrict__ src, float4* __restrict__ dst, int n4) {
    int i = blockIdx.x * blockDim.x + threadIdx.x;
    if (i >= n4) return;
    float4 v = src[i];
    uint32_t a, b, c, d;
    asm("cvt.rna.tf32.f32 %0, %1;" : "=r"(a) : "f"(v.x));
    asm("cvt.rna.tf32.f32 %0, %1;" : "=r"(b) : "f"(v.y));
    asm("cvt.rna.tf32.f32 %0, %1;" : "=r"(c) : "f"(v.z));
    asm("cvt.rna.tf32.f32 %0, %1;" : "=r"(d) : "f"(v.w));
    float4 o;
    o.x = __uint_as_float(a); o.y = __uint_as_float(b);
    o.z = __uint_as_float(c); o.w = __uint_as_float(d);
    dst[i] = o;
}

// ---------------- stage loader ----------------
template<bool GATE>
__device__ __forceinline__ void load_stage(float* smA, float* smB,
        const float* __restrict__ W, int blockM, int blockN, int k0, int tid)
{
    const int row = tid >> 1;          // 0..127
    const int u0 = (tid & 1) * 4;      // 16B units

    const float* Aptr = g_cvt_in;
    int ka = k0;
    if (GATE && k0 >= IN_D) { Aptr = g_cvt_st; ka = k0 - IN_D; }
    const float* asrc = Aptr + (size_t)(blockM + row) * 2048 + ka;
    const size_t bld = GATE ? (size_t)CAT_D : (size_t)IN_D;
    const float* bsrc = W + (size_t)(blockN + row) * bld + k0;

    uint32_t adst = smem_u32(smA + (size_t)row * LDSW);
    uint32_t bdst = smem_u32(smB + (size_t)row * LDSW);
#pragma unroll
    for (int j = 0; j < 4; j++) {
        const int u = u0 + j;
        cp16(adst + (uint32_t)u * 16, asrc + u * 4);
        cp16(bdst + (uint32_t)u * 16, bsrc + u * 4);
    }
}

// ---------------- stage compute: warp tile 64x32 ----------------
__device__ __forceinline__ void compute_stage(const float* smA, const float* smB,
        float acc[4][4][4], int m0, int n0, int g, int tig)
{
#pragma unroll
    for (int kk = 0; kk < 4; kk++) {
        uint32_t af[4][4], bf[4][2];
#pragma unroll
        for (int i = 0; i < 4; i++) {
            const float* base = smA + (size_t)(m0 + i * 16 + g) * LDSW + kk * 8 + tig;
            af[i][0] = __float_as_uint(base[0]);
            af[i][1] = __float_as_uint(base[8 * LDSW]);
            af[i][2] = __float_as_uint(base[4]);
            af[i][3] = __float_as_uint(base[8 * LDSW + 4]);
        }
#pragma unroll
        for (int j = 0; j < 4; j++) {
            const float* base = smB + (size_t)(n0 + j * 8 + g) * LDSW + kk * 8 + tig;
            bf[j][0] = __float_as_uint(base[0]);
            bf[j][1] = __float_as_uint(base[4]);
        }
#pragma unroll
        for (int i = 0; i < 4; i++)
#pragma unroll
            for (int j = 0; j < 4; j++)
                mma8(acc[i][j], af[i], bf[j]);
    }
}

// Output layout (floats): new_h | concat | pre_gate | gate | values | pre_h
template<bool GATE>
__global__ __launch_bounds__(NT, 2)
void gemm_kernel(const float* __restrict__ state,
                 const float* __restrict__ W, const float* __restrict__ bias,
                 float* __restrict__ out)
{
    extern __shared__ float sm[];
    const int tid = threadIdx.x;
    const int wid = tid >> 5, lane = tid & 31;
    const int g = lane >> 2, tig = lane & 3;
    const int m0 = (wid >> 2) * 64;    // 0 or 64
    const int n0 = (wid & 3) * 32;     // 0..96
    const int blockM = blockIdx.y * BM;
    const int blockN = blockIdx.x * BN;

    const int KT = (GATE ? CAT_D : IN_D) / BK;

    float* A0 = sm;
    float* B0 = sm + BM * LDSW;
    float* A1 = sm + (BM + BN) * LDSW;
    float* B1 = A1 + BM * LDSW;

    float acc[4][4][4];
#pragma unroll
    for (int i = 0; i < 4; i++)
#pragma unroll
        for (int j = 0; j < 4; j++)
#pragma unroll
            for (int t = 0; t < 4; t++) acc[i][j][t] = 0.f;

    load_stage<GATE>(A0, B0, W, blockM, blockN, 0, tid);
    CP_COMMIT();

    // single-sync pipeline: wait -> sync -> issue next load -> compute
    for (int kt = 0; kt < KT; kt++) {
        CP_WAIT0();
        __syncthreads();
        if (kt + 1 < KT) {
            float* nA = (kt & 1) ? A0 : A1;
            float* nB = (kt & 1) ? B0 : B1;
            load_stage<GATE>(nA, nB, W, blockM, blockN, (kt + 1) * BK, tid);
            CP_COMMIT();
        }
        float* cA = (kt & 1) ? A1 : A0;
        float* cB = (kt & 1) ? B1 : B0;
        compute_stage(cA, cB, acc, m0, n0, g, tig);
    }

    // ---------------- fused epilogue ----------------
    const size_t BH = (size_t)BSZ * H_D;
    const size_t BC = (size_t)BSZ * CAT_D;

    if (GATE) {
        float* out_pg = out + BH + BC;
        float* out_gt = out_pg + BH;
#pragma unroll
        for (int i = 0; i < 4; i++) {
            const int r0 = blockM + m0 + i * 16 + g;
#pragma unroll
            for (int j = 0; j < 4; j++) {
                const int c = blockN + n0 + j * 8 + tig * 2;
                const float b0 = bias[c], b1 = bias[c + 1];
                float pg0 = acc[i][j][0] + b0, pg1 = acc[i][j][1] + b1;
                float pg2 = acc[i][j][2] + b0, pg3 = acc[i][j][3] + b1;
                const size_t o0 = (size_t)r0 * H_D + c;
                const size_t o1 = (size_t)(r0 + 8) * H_D + c;
                *(float2*)(out_pg + o0) = make_float2(pg0, pg1);
                *(float2*)(out_pg + o1) = make_float2(pg2, pg3);
                *(float2*)(out_gt + o0) = make_float2(fminf(fmaxf(pg0, 0.f), 1.f),
                                                      fminf(fmaxf(pg1, 0.f), 1.f));
                *(float2*)(out_gt + o1) = make_float2(fminf(fmaxf(pg2, 0.f), 1.f),
                                                      fminf(fmaxf(pg3, 0.f), 1.f));
            }
        }
    } else {
        // value kernel runs AFTER gate kernel: gate region of out is final.
        float* out_newh = out;
        float* out_gt   = out + 2 * BH + BC;
        float* out_val  = out + 3 * BH + BC;
        float* out_ph   = out + 4 * BH + BC;
#pragma unroll
        for (int i = 0; i < 4; i++) {
            const int r0 = blockM + m0 + i * 16 + g;
#pragma unroll
            for (int j = 0; j < 4; j++) {
                const int c = blockN + n0 + j * 8 + tig * 2;
                const size_t o0 = (size_t)r0 * H_D + c;
                const size_t o1 = (size_t)(r0 + 8) * H_D + c;
                float v0 = tanhf(acc[i][j][0]), v1 = tanhf(acc[i][j][1]);
                float v2 = tanhf(acc[i][j][2]), v3 = tanhf(acc[i][j][3]);
                float2 ga = *(const float2*)(out_gt + o0);
                float2 gb = *(const float2*)(out_gt + o1);
                float2 sa = *(const float2*)(state + o0);
                float2 sb = *(const float2*)(state + o1);
                float ph0 = sa.x * (1.f - ga.x) + v0 * ga.x;
                float ph1 = sa.y * (1.f - ga.y) + v1 * ga.y;
                float ph2 = sb.x * (1.f - gb.x) + v2 * gb.x;
                float ph3 = sb.y * (1.f - gb.y) + v3 * gb.y;
                *(float2*)(out_val + o0) = make_float2(v0, v1);
                *(float2*)(out_val + o1) = make_float2(v2, v3);
                *(float2*)(out_ph + o0) = make_float2(ph0, ph1);
                *(float2*)(out_ph + o1) = make_float2(ph2, ph3);
                *(float2*)(out_newh + o0) = make_float2(fmaxf(ph0, 0.f), fmaxf(ph1, 0.f));
                *(float2*)(out_newh + o1) = make_float2(fmaxf(ph2, 0.f), fmaxf(ph3, 0.f));
            }
        }
    }
}

// ---------------- concat kernel ----------------
__global__ void concat_copy_kernel(const float* __restrict__ input,
                                   const float* __restrict__ state,
                                   float* __restrict__ concat_out)
{
    const int COLS4 = CAT_D / 4;
    const int HALF4 = IN_D / 4;
    size_t idx = (size_t)blockIdx.x * blockDim.x + threadIdx.x;
    const size_t total = (size_t)BSZ * COLS4;
    if (idx >= total) return;
    size_t b = idx / COLS4;
    int c = (int)(idx % COLS4);
    float4 v;
    if (c < HALF4) v = *(const float4*)(input + b * IN_D + (size_t)c * 4);
    else           v = *(const float4*)(state + b * H_D + (size_t)(c - HALF4) * 4);
    *(float4*)(concat_out + b * CAT_D + (size_t)c * 4) = v;
}

extern "C" void kernel_launch(void* const* d_in, const int* in_sizes, int n_in,
                              void* d_out, int out_size)
{
    const float* input = (const float*)d_in[0];
    const float* state = (const float*)d_in[1];
    const float* gw    = (const float*)d_in[2];
    const float* bias  = (const float*)d_in[3];
    const float* wi    = (const float*)d_in[4];
    float* out = (float*)d_out;

    void *p_in, *p_st, *p_gw, *p_wi;
    cudaGetSymbolAddress(&p_in, g_cvt_in);
    cudaGetSymbolAddress(&p_st, g_cvt_st);
    cudaGetSymbolAddress(&p_gw, g_cvt_gw);
    cudaGetSymbolAddress(&p_wi, g_cvt_wi);

    {
        int n4 = BSZ * IN_D / 4;
        tf32_round_kernel<<<(n4 + 255) / 256, 256>>>((const float4*)input, (float4*)p_in, n4);
        n4 = BSZ * H_D / 4;
        tf32_round_kernel<<<(n4 + 255) / 256, 256>>>((const float4*)state, (float4*)p_st, n4);
        n4 = H_D * CAT_D / 4;
        tf32_round_kernel<<<(n4 + 255) / 256, 256>>>((const float4*)gw, (float4*)p_gw, n4);
        n4 = H_D * IN_D / 4;
        tf32_round_kernel<<<(n4 + 255) / 256, 256>>>((const float4*)wi, (float4*)p_wi, n4);
    }

    const int smem_bytes = 2 * (BM + BN) * LDSW * sizeof(float);   // 73728
    cudaFuncSetAttribute(gemm_kernel<true>,  cudaFuncAttributeMaxDynamicSharedMemorySize, smem_bytes);
    cudaFuncSetAttribute(gemm_kernel<false>, cudaFuncAttributeMaxDynamicSharedMemorySize, smem_bytes);

    dim3 grid(H_D / BN, BSZ / BM);   // (16, 64)
    gemm_kernel<true><<<grid, NT, smem_bytes>>>(state, gw, bias, out);
    gemm_kernel<false><<<grid, NT, smem_bytes>>>(state, wi, bias, out);

    const size_t BH = (size_t)BSZ * H_D;
    float* concat_out = out + BH;
    const size_t total4 = (size_t)BSZ * (CAT_D / 4);
    concat_copy_kernel<<<(int)((total4 + 255) / 256), 256>>>(input, state, concat_out);
}